// round 5
// baseline (speedup 1.0000x reference)
#include <cuda_runtime.h>

// ButterflyLinear, fully fused single kernel.
// Math: stage 0 pairs (j, j^1); stages 1..11 all pair (j, j^2) => the whole
// 12-stage network is block-diagonal in 4-element groups. Each thread owns
// one group g: it folds the 12 stage 2x2s into a 4x4 A_g in registers
// (24 float4 loads from the L2-resident 768KB factor array + ~180 FMA),
// then streams T_PER=64 tokens: out = A_g * x + bias. Fusing kills the
// separate precompute kernel + node-serialization gap (~9us measured).

#define TOKENS 8192
#define NCOLS  4096
#define DEPTH  12
#define GROUPS (NCOLS / 4)   // 1024
#define PAIRS  (NCOLS / 2)   // 2048 factor pairs per stage
#define T_PER  64            // tokens per thread -> 512 blocks total

// ---------------------------------------------------------------------------
// factors layout: F[stage][pair][c][d] as float4 per pair:
//   f.x=f[0][0], f.y=f[0][1], f.z=f[1][0], f.w=f[1][1]
// Stage semantics: y[d] = sum_c pair_in[c] * f[c][d]
// ---------------------------------------------------------------------------
__global__ void __launch_bounds__(256)
butterfly_fused(const float4* __restrict__ F4,
                const float4* __restrict__ x,
                const float4* __restrict__ bias4,
                float4* __restrict__ out) {
    int g  = blockIdx.x * blockDim.x + threadIdx.x;  // 0..GROUPS-1
    int t0 = blockIdx.y * T_PER;
    int j0 = 4 * g;

    // ---- kick off the first stream loads EARLY (independent of the fold) ----
    const float4* xp = x   + (size_t)t0 * GROUPS + g;
    float4*       op = out + (size_t)t0 * GROUPS + g;
    float4 v0 = __ldcs(xp + 0 * GROUPS);
    float4 v1 = __ldcs(xp + 1 * GROUPS);
    float4 v2 = __ldcs(xp + 2 * GROUPS);
    float4 v3 = __ldcs(xp + 3 * GROUPS);
    float4 b  = bias4[g];

    // ---- fold the 12 stages into a 4x4 (row-major: a{row}{col}) ----
    float a00, a01, a02, a03, a10, a11, a12, a13;
    float a20, a21, a22, a23, a30, a31, a32, a33;
    {
        float4 f0 = __ldg(F4 + 2 * g);
        float4 f1 = __ldg(F4 + 2 * g + 1);
        a00 = f0.x; a01 = f0.z; a02 = 0.f;  a03 = 0.f;
        a10 = f0.y; a11 = f0.w; a12 = 0.f;  a13 = 0.f;
        a20 = 0.f;  a21 = 0.f;  a22 = f1.x; a23 = f1.z;
        a30 = 0.f;  a31 = 0.f;  a32 = f1.y; a33 = f1.w;
    }
    #pragma unroll
    for (int s = 1; s < DEPTH; s++) {
        int block = 1 << (s + 1);
        int pA = ((j0 >> (s + 1)) << s) | ((j0 & (block - 1)) >> 2);
        int pB = pA + (1 << (s - 1));
        float4 fA = __ldg(F4 + s * PAIRS + pA);   // mixes rows (0,2)
        float4 fB = __ldg(F4 + s * PAIRS + pB);   // mixes rows (1,3)
        float r0, r2;
        r0 = a00; r2 = a20; a00 = fA.x*r0 + fA.z*r2; a20 = fA.y*r0 + fA.w*r2;
        r0 = a01; r2 = a21; a01 = fA.x*r0 + fA.z*r2; a21 = fA.y*r0 + fA.w*r2;
        r0 = a02; r2 = a22; a02 = fA.x*r0 + fA.z*r2; a22 = fA.y*r0 + fA.w*r2;
        r0 = a03; r2 = a23; a03 = fA.x*r0 + fA.z*r2; a23 = fA.y*r0 + fA.w*r2;
        float r1, r3;
        r1 = a10; r3 = a30; a10 = fB.x*r1 + fB.z*r3; a30 = fB.y*r1 + fB.w*r3;
        r1 = a11; r3 = a31; a11 = fB.x*r1 + fB.z*r3; a31 = fB.y*r1 + fB.w*r3;
        r1 = a12; r3 = a32; a12 = fB.x*r1 + fB.z*r3; a32 = fB.y*r1 + fB.w*r3;
        r1 = a13; r3 = a33; a13 = fB.x*r1 + fB.z*r3; a33 = fB.y*r1 + fB.w*r3;
    }

    // ---- stream T_PER tokens: software-pipelined chunks of 4 ----
    #pragma unroll 4
    for (int ii = 0; ii < T_PER; ii += 4) {
        float4 r0, r1, r2, r3;
        r0.x = b.x + v0.x*a00 + v0.y*a01 + v0.z*a02 + v0.w*a03;
        r0.y = b.y + v0.x*a10 + v0.y*a11 + v0.z*a12 + v0.w*a13;
        r0.z = b.z + v0.x*a20 + v0.y*a21 + v0.z*a22 + v0.w*a23;
        r0.w = b.w + v0.x*a30 + v0.y*a31 + v0.z*a32 + v0.w*a33;

        r1.x = b.x + v1.x*a00 + v1.y*a01 + v1.z*a02 + v1.w*a03;
        r1.y = b.y + v1.x*a10 + v1.y*a11 + v1.z*a12 + v1.w*a13;
        r1.z = b.z + v1.x*a20 + v1.y*a21 + v1.z*a22 + v1.w*a23;
        r1.w = b.w + v1.x*a30 + v1.y*a31 + v1.z*a32 + v1.w*a33;

        r2.x = b.x + v2.x*a00 + v2.y*a01 + v2.z*a02 + v2.w*a03;
        r2.y = b.y + v2.x*a10 + v2.y*a11 + v2.z*a12 + v2.w*a13;
        r2.z = b.z + v2.x*a20 + v2.y*a21 + v2.z*a22 + v2.w*a23;
        r2.w = b.w + v2.x*a30 + v2.y*a31 + v2.z*a32 + v2.w*a33;

        r3.x = b.x + v3.x*a00 + v3.y*a01 + v3.z*a02 + v3.w*a03;
        r3.y = b.y + v3.x*a10 + v3.y*a11 + v3.z*a12 + v3.w*a13;
        r3.z = b.z + v3.x*a20 + v3.y*a21 + v3.z*a22 + v3.w*a23;
        r3.w = b.w + v3.x*a30 + v3.y*a31 + v3.z*a32 + v3.w*a33;

        // next chunk's loads in flight before the stores
        if (ii + 4 < T_PER) {
            v0 = __ldcs(xp + (size_t)(ii + 4) * GROUPS);
            v1 = __ldcs(xp + (size_t)(ii + 5) * GROUPS);
            v2 = __ldcs(xp + (size_t)(ii + 6) * GROUPS);
            v3 = __ldcs(xp + (size_t)(ii + 7) * GROUPS);
        }

        __stcs(op + (size_t)(ii + 0) * GROUPS, r0);
        __stcs(op + (size_t)(ii + 1) * GROUPS, r1);
        __stcs(op + (size_t)(ii + 2) * GROUPS, r2);
        __stcs(op + (size_t)(ii + 3) * GROUPS, r3);
    }
}

// ---------------------------------------------------------------------------
extern "C" void kernel_launch(void* const* d_in, const int* in_sizes, int n_in,
                              void* d_out, int out_size) {
    const float* x = nullptr;
    const float* factors = nullptr;
    const float* bias = nullptr;
    for (int i = 0; i < n_in; i++) {
        if (in_sizes[i] == TOKENS * NCOLS)            x = (const float*)d_in[i];
        else if (in_sizes[i] == DEPTH * PAIRS * 4)    factors = (const float*)d_in[i];
        else if (in_sizes[i] == NCOLS)                bias = (const float*)d_in[i];
    }

    dim3 grid(GROUPS / 256, TOKENS / T_PER);   // (4, 128) = 512 blocks
    butterfly_fused<<<grid, 256>>>((const float4*)factors,
                                   (const float4*)x,
                                   (const float4*)bias,
                                   (float4*)d_out);
}